// round 6
// baseline (speedup 1.0000x reference)
#include <cuda_runtime.h>
#include <math_constants.h>

typedef unsigned long long u64;
typedef unsigned int u32;

// Problem constants
#define Bb 8
#define Ll 256
#define Aa 15
#define Kk 9
#define TB 16
#define NTILES 136                 // triangular 16x16 tiles
#define DIST_CTAS (Bb * NTILES)    // 1088

// Output layout (float32, concatenated flattened tuple)
#define OFF_BATCH   30720
#define OFF_EDGES   32768
#define OFF_ATTR    106496
#define N_OUT       696320
#define EDGES_HALF  18432
#define EDGES_ROW   36864

#define KNN_CTAS    512            // 4096 warps
#define FILL4_CTAS  680            // N_OUT/4/256

// Scratch: rank-equivalent block distance (= d2min/2, clamped >= 0), [B, L, L]
__device__ float g_d2min[Bb * Ll * Ll];

// ---- packed helpers ------------------------------------------------------
static __device__ __forceinline__ u64 bcast2(float v) {
    u64 r; asm("mov.b64 %0, {%1, %1};" : "=l"(r) : "f"(v)); return r;
}
static __device__ __forceinline__ u64 ffma2(u64 a, u64 b, u64 c) {
    u64 d; asm("fma.rn.f32x2 %0, %1, %2, %3;" : "=l"(d) : "l"(a), "l"(b), "l"(c)); return d;
}
static __device__ __forceinline__ float minhalves(u64 p) {
    float lo, hi; asm("mov.b64 {%0, %1}, %2;" : "=f"(lo), "=f"(hi) : "l"(p));
    return fminf(lo, hi);
}

// ---------------------------------------------------------------------------
// Kernel 1: block-pair min half-squared-distance, triangular tiles, PURE.
// d2' = hn_i + hn_j - <xi,xj> (rank-equivalent). J side padded to 16 atoms
// (dummy hn=1e30) stored as plain float rows of 16 -> u64 LDS.64 reads give
// packed pairs with ZERO marshaling. 3 FFMA2 per 2 atom pairs; min tree in
// scalar FMNMX (register-pair unpack free).
// ---------------------------------------------------------------------------
__global__ void __launch_bounds__(256) dist_kernel(const float* __restrict__ pos) {
    __shared__ float4 sI[TB * Aa];
    __shared__ float sJx[TB * 16], sJy[TB * 16], sJz[TB * 16], sJn[TB * 16];

    const int b = blockIdx.x / NTILES;
    int r = blockIdx.x % NTILES, ti = 0;
    while (r >= (TB - ti)) { r -= (TB - ti); ti++; }
    const int tj = ti + r;
    const int i0 = ti * TB, j0 = tj * TB;

    const int t = threadIdx.x;
    if (t < TB * Aa) {
        const int blk = t / Aa;
        const int at  = t % Aa;
        {
            const float* p = pos + ((size_t)((b * Ll + i0 + blk) * Aa + at)) * 3;
            float x = p[0], y = p[1], z = p[2];
            sI[t] = make_float4(x, y, z, 0.5f * (x * x + y * y + z * z));
        }
        {
            const float* p = pos + ((size_t)((b * Ll + j0 + blk) * Aa + at)) * 3;
            float x = p[0], y = p[1], z = p[2];
            const int s = blk * 16 + at;
            sJx[s] = x; sJy[s] = y; sJz[s] = z;
            sJn[s] = 0.5f * (x * x + y * y + z * z);
        }
    } else {  // threads 240..255: dummy 16th J atom per block
        const int blk = t - TB * Aa;
        const int s = blk * 16 + 15;
        sJx[s] = 0.0f; sJy[s] = 0.0f; sJz[s] = 0.0f; sJn[s] = 1e30f;
    }
    __syncthreads();

    const int ii = t >> 4;
    const int jj = t & 15;

    // J-side 8 packed pairs per component, loaded directly as u64 (no packs)
    u64 jx2[8], jy2[8], jz2[8], jn2[8];
    {
        const u64* px = (const u64*)(sJx + jj * 16);
        const u64* py = (const u64*)(sJy + jj * 16);
        const u64* pz = (const u64*)(sJz + jj * 16);
        const u64* pn = (const u64*)(sJn + jj * 16);
#pragma unroll
        for (int c = 0; c < 8; c++) {
            jx2[c] = px[c]; jy2[c] = py[c]; jz2[c] = pz[c]; jn2[c] = pn[c];
        }
    }

    float m0 = CUDART_INF_F, m1 = CUDART_INF_F;
#pragma unroll
    for (int a = 0; a < Aa; a++) {
        const float4 I = sI[ii * Aa + a];
        const u64 nx = bcast2(-I.x);
        const u64 ny = bcast2(-I.y);
        const u64 nz = bcast2(-I.z);

        u64 a0 = ffma2(nz, jz2[0], ffma2(ny, jy2[0], ffma2(nx, jx2[0], jn2[0])));
        u64 a1 = ffma2(nz, jz2[1], ffma2(ny, jy2[1], ffma2(nx, jx2[1], jn2[1])));
        u64 a2 = ffma2(nz, jz2[2], ffma2(ny, jy2[2], ffma2(nx, jx2[2], jn2[2])));
        u64 a3 = ffma2(nz, jz2[3], ffma2(ny, jy2[3], ffma2(nx, jx2[3], jn2[3])));
        u64 a4 = ffma2(nz, jz2[4], ffma2(ny, jy2[4], ffma2(nx, jx2[4], jn2[4])));
        u64 a5 = ffma2(nz, jz2[5], ffma2(ny, jy2[5], ffma2(nx, jx2[5], jn2[5])));
        u64 a6 = ffma2(nz, jz2[6], ffma2(ny, jy2[6], ffma2(nx, jx2[6], jn2[6])));
        u64 a7 = ffma2(nz, jz2[7], ffma2(ny, jy2[7], ffma2(nx, jx2[7], jn2[7])));

        const float t0 = fminf(minhalves(a0), minhalves(a1));
        const float t1 = fminf(minhalves(a2), minhalves(a3));
        const float t2 = fminf(minhalves(a4), minhalves(a5));
        const float t3 = fminf(minhalves(a6), minhalves(a7));
        const float mloc = fminf(fminf(t0, t1), fminf(t2, t3)) + I.w;
        if (a & 1) m1 = fminf(m1, mloc); else m0 = fminf(m0, mloc);
    }
    const float m = fmaxf(fminf(m0, m1), 0.0f);

    float* g = g_d2min + (size_t)b * Ll * Ll;
    g[(size_t)(i0 + ii) * Ll + (j0 + jj)] = m;
    g[(size_t)(j0 + jj) * Ll + (i0 + ii)] = m;
}

// ---------------------------------------------------------------------------
// Kernel 2: KNN (CTAs [0, KNN_CTAS)) + float4 static fills (the rest).
// KNN: one warp per (type,b,l); coalesced loads (j = lane + 32u); u64 keys
// (d2_bits<<32)|j; per-lane Batcher sort-8; 9 rounds of 2x REDUX.MIN.U32.
// Fill: one float4 per thread; all region boundaries are 0 mod 4.
// ---------------------------------------------------------------------------
#define CE(x, y) { u64 aa_ = x, bb_ = y; bool g_ = aa_ > bb_; x = g_ ? bb_ : aa_; y = g_ ? aa_ : bb_; }

__global__ void __launch_bounds__(256) knn_fill_kernel(const int* __restrict__ frag,
                                                       const float* __restrict__ edge_emb,
                                                       float* __restrict__ out) {
    if (blockIdx.x >= KNN_CTAS) {
        const int q = (blockIdx.x - KNN_CTAS) * 256 + threadIdx.x;   // float4 index
        const int i = q << 2;
        if (i >= N_OUT) return;
        float4 v;
        if (i < OFF_BATCH) {
            v.x = (float)(i / Aa); v.y = (float)((i + 1) / Aa);
            v.z = (float)((i + 2) / Aa); v.w = (float)((i + 3) / Aa);
        } else if (i < OFF_EDGES) {
            const int e = i - OFF_BATCH;            // 4-aligned; 256-divisible regions
            const float bv = (float)(e >> 8);
            v.x = bv; v.y = bv; v.z = bv; v.w = bv; // (e>>8) constant within a quad
        } else if (i < OFF_ATTR) {
            const int e   = i - OFF_EDGES;
            const int row = e / EDGES_ROW;
            const int c   = e % EDGES_ROW;
            const int p   = c % EDGES_HALF;
            if (row == 0) {
                // src = l + b*L ; l = (p/K)%L varies within the quad
                const int p0 = p;
                float s[4];
#pragma unroll
                for (int u = 0; u < 4; u++) {
                    const int pu = p0 + u;
                    s[u] = (float)(((pu / Kk) % Ll) + (pu / (Ll * Kk)) * Ll);
                }
                v.x = s[0]; v.y = s[1]; v.z = s[2]; v.w = s[3];
            } else {
                v.x = v.y = v.z = v.w = 0.0f;       // dst overwritten by KNN
            }
        } else {
            const int e    = i - OFF_ATTR;
            const int type = ((e >> 4) >= EDGES_HALF) ? 1 : 0;
            v = *(const float4*)(edge_emb + type * 16 + (e & 12));
        }
        *(float4*)(out + i) = v;
        return;
    }

    const int gwarp = (blockIdx.x << 3) + (threadIdx.x >> 5);
    const int lane  = threadIdx.x & 31;

    const int type = gwarp >> 11;
    const int rem  = gwarp & 2047;
    const int b    = rem >> 8;
    const int l    = rem & 255;

    const int fi   = frag[(b << 8) + l];
    const int segi = (fi == 2) ? 1 : fi;

    const float* drow = g_d2min + ((size_t)b << 16) + ((size_t)l << 8);
    const int*   frow = frag + (b << 8);

    u64 k0, k1, k2, k3, k4, k5, k6, k7;
    {
        u64 kk[8];
#pragma unroll
        for (int u = 0; u < 8; u++) {
            const int j  = lane + (u << 5);
            const int fj = frow[j];
            const int segj = (fj == 2) ? 1 : fj;
            const bool ok = (type == 0) ? (segj == segi && j != l) : (segj != segi);
            const float v = ok ? drow[j] : CUDART_INF_F;
            kk[u] = ((u64)__float_as_uint(v) << 32) | (u32)j;
        }
        k0 = kk[0]; k1 = kk[1]; k2 = kk[2]; k3 = kk[3];
        k4 = kk[4]; k5 = kk[5]; k6 = kk[6]; k7 = kk[7];
    }

    // Batcher odd-even merge sort, 19 compare-exchanges, ascending
    CE(k0,k1) CE(k2,k3) CE(k4,k5) CE(k6,k7)
    CE(k0,k2) CE(k1,k3) CE(k4,k6) CE(k5,k7)
    CE(k1,k2) CE(k5,k6)
    CE(k0,k4) CE(k1,k5) CE(k2,k6) CE(k3,k7)
    CE(k2,k4) CE(k3,k5)
    CE(k1,k2) CE(k3,k4) CE(k5,k6)

    const size_t base = (size_t)OFF_EDGES + EDGES_ROW
                      + (size_t)type * EDGES_HALF
                      + (size_t)((b << 8) + l) * Kk;

#pragma unroll
    for (int k = 0; k < Kk; k++) {
        const u32 hd = (u32)(k0 >> 32);
        const u32 wd = __reduce_min_sync(0xffffffffu, hd);
        const u32 cj = (hd == wd) ? (u32)k0 : 0xffffffffu;
        const u32 wj = __reduce_min_sync(0xffffffffu, cj);
        if (lane == 0) out[base + k] = (float)(wj + (b << 8));
        if (hd == wd && (u32)k0 == wj) {
            k0 = k1; k1 = k2; k2 = k3; k3 = k4;
            k4 = k5; k5 = k6; k6 = k7; k7 = ~0ULL;
        }
    }
}

// ---------------------------------------------------------------------------
extern "C" void kernel_launch(void* const* d_in, const int* in_sizes, int n_in,
                              void* d_out, int out_size) {
    const float* pos      = (const float*)d_in[0];
    const int*   frag     = (const int*)  d_in[6];
    const float* edge_emb = (const float*)d_in[7];
    float* out = (float*)d_out;

    dist_kernel<<<DIST_CTAS, 256>>>(pos);
    knn_fill_kernel<<<KNN_CTAS + FILL4_CTAS, 256>>>(frag, edge_emb, out);

    (void)in_sizes; (void)n_in; (void)out_size;
}

// round 7
// speedup vs baseline: 1.3509x; 1.3509x over previous
#include <cuda_runtime.h>
#include <math_constants.h>

typedef unsigned long long u64;
typedef unsigned int u32;

// Problem constants
#define Bb 8
#define Ll 256
#define Aa 15
#define Kk 9
#define TB 16
#define NTILES 136                 // triangular 16x16 tiles
#define DIST_CTAS (Bb * NTILES)    // 1088

// Output layout (float32, concatenated flattened tuple)
#define OFF_BATCH   30720
#define OFF_EDGES   32768
#define OFF_ATTR    106496
#define N_OUT       696320
#define EDGES_HALF  18432
#define EDGES_ROW   36864

#define KNN_CTAS    256            // 2048 warps, one per (b,l), both types
#define FILL4_CTAS  680            // N_OUT/4/256

// Scratch: rank-equivalent block distance (= d2min/2, clamped >= 0), [B, L, L]
__device__ float g_d2min[Bb * Ll * Ll];

// ---------------------------------------------------------------------------
// Kernel 1: block-pair min half-squared-distance, triangular tiles (scalar).
// d2' = hn_i + hn_j - <xi,xj> (rank-equivalent to d2 for per-row top-k).
// 3 FFMA + 1 FMNMX per atom pair; 2 inner + 2 outer min accumulators for ILP.
// ---------------------------------------------------------------------------
__global__ void __launch_bounds__(256) dist_kernel(const float* __restrict__ pos) {
    __shared__ float4 sI[TB * Aa];
    __shared__ float4 sJ[TB * Aa];

    const int b = blockIdx.x / NTILES;
    int r = blockIdx.x % NTILES, ti = 0;
    while (r >= (TB - ti)) { r -= (TB - ti); ti++; }
    const int tj = ti + r;
    const int i0 = ti * TB, j0 = tj * TB;

    const int t = threadIdx.x;
    if (t < TB * Aa) {
        const int blk = t / Aa;
        const int at  = t % Aa;
        {
            const float* p = pos + ((size_t)((b * Ll + i0 + blk) * Aa + at)) * 3;
            float x = p[0], y = p[1], z = p[2];
            sI[t] = make_float4(x, y, z, 0.5f * (x * x + y * y + z * z));
        }
        {
            const float* p = pos + ((size_t)((b * Ll + j0 + blk) * Aa + at)) * 3;
            float x = p[0], y = p[1], z = p[2];
            sJ[t] = make_float4(x, y, z, 0.5f * (x * x + y * y + z * z));
        }
    }
    __syncthreads();

    const int ii = t >> 4;
    const int jj = t & 15;

    // J-side atoms register-resident
    float jx[Aa], jy[Aa], jz[Aa], jn[Aa];
#pragma unroll
    for (int a = 0; a < Aa; a++) {
        const float4 v = sJ[jj * Aa + a];
        jx[a] = v.x; jy[a] = v.y; jz[a] = v.z; jn[a] = v.w;
    }

    float m0 = CUDART_INF_F, m1 = CUDART_INF_F;
#pragma unroll
    for (int a = 0; a < Aa; a++) {
        const float4 I = sI[ii * Aa + a];
        float mA = fmaf(-I.z, jz[0], fmaf(-I.y, jy[0], fmaf(-I.x, jx[0], jn[0])));
        float mB = fmaf(-I.z, jz[1], fmaf(-I.y, jy[1], fmaf(-I.x, jx[1], jn[1])));
#pragma unroll
        for (int c = 2; c + 1 < Aa; c += 2) {
            mA = fminf(mA, fmaf(-I.z, jz[c],   fmaf(-I.y, jy[c],   fmaf(-I.x, jx[c],   jn[c]))));
            mB = fminf(mB, fmaf(-I.z, jz[c+1], fmaf(-I.y, jy[c+1], fmaf(-I.x, jx[c+1], jn[c+1]))));
        }
        mA = fminf(mA, fmaf(-I.z, jz[Aa-1], fmaf(-I.y, jy[Aa-1], fmaf(-I.x, jx[Aa-1], jn[Aa-1]))));
        const float mloc = fminf(mA, mB) + I.w;
        if (a & 1) m1 = fminf(m1, mloc); else m0 = fminf(m0, mloc);
    }
    const float m = fmaxf(fminf(m0, m1), 0.0f);

    float* g = g_d2min + (size_t)b * Ll * Ll;
    g[(size_t)(i0 + ii) * Ll + (j0 + jj)] = m;
    g[(size_t)(j0 + jj) * Ll + (i0 + ii)] = m;
}

// ---------------------------------------------------------------------------
// Kernel 2: dual-stream KNN (CTAs [0, KNN_CTAS)) + float4 fills (the rest).
// One warp handles BOTH edge types for one (b,l): shared d2/frag loads, two
// independent extraction chains interleaved for latency hiding.
// Keys (d2_bits<<32)|j : d2 >= 0 so unsigned order == float order; low bits
// give exact lowest-index tie-break (matches top_k stability).
// ---------------------------------------------------------------------------
#define CE(x, y) { u64 aa_ = x, bb_ = y; bool g_ = aa_ > bb_; x = g_ ? bb_ : aa_; y = g_ ? aa_ : bb_; }
#define SORT8(q) \
    CE(q[0],q[1]) CE(q[2],q[3]) CE(q[4],q[5]) CE(q[6],q[7]) \
    CE(q[0],q[2]) CE(q[1],q[3]) CE(q[4],q[6]) CE(q[5],q[7]) \
    CE(q[1],q[2]) CE(q[5],q[6]) \
    CE(q[0],q[4]) CE(q[1],q[5]) CE(q[2],q[6]) CE(q[3],q[7]) \
    CE(q[2],q[4]) CE(q[3],q[5]) \
    CE(q[1],q[2]) CE(q[3],q[4]) CE(q[5],q[6])

__global__ void __launch_bounds__(256) knn_fill_kernel(const int* __restrict__ frag,
                                                       const float* __restrict__ edge_emb,
                                                       float* __restrict__ out) {
    if (blockIdx.x >= KNN_CTAS) {
        const int q = (blockIdx.x - KNN_CTAS) * 256 + threadIdx.x;   // float4 index
        const int i = q << 2;
        if (i >= N_OUT) return;
        float4 v;
        if (i < OFF_BATCH) {
            v.x = (float)(i / Aa); v.y = (float)((i + 1) / Aa);
            v.z = (float)((i + 2) / Aa); v.w = (float)((i + 3) / Aa);
        } else if (i < OFF_EDGES) {
            const float bv = (float)((i - OFF_BATCH) >> 8);
            v.x = bv; v.y = bv; v.z = bv; v.w = bv;
        } else if (i < OFF_ATTR) {
            const int e   = i - OFF_EDGES;
            const int row = e / EDGES_ROW;
            const int c   = e % EDGES_ROW;
            const int p   = c % EDGES_HALF;
            if (row == 0) {
                float s[4];
#pragma unroll
                for (int u = 0; u < 4; u++) {
                    const int pu = p + u;
                    s[u] = (float)(((pu / Kk) % Ll) + (pu / (Ll * Kk)) * Ll);
                }
                v.x = s[0]; v.y = s[1]; v.z = s[2]; v.w = s[3];
            } else {
                v.x = v.y = v.z = v.w = 0.0f;       // dst overwritten by KNN
            }
        } else {
            const int e    = i - OFF_ATTR;
            const int type = ((e >> 4) >= EDGES_HALF) ? 1 : 0;
            v = *(const float4*)(edge_emb + type * 16 + (e & 12));
        }
        *(float4*)(out + i) = v;
        return;
    }

    const int gwarp = (blockIdx.x << 3) + (threadIdx.x >> 5);   // 0..2047
    const int lane  = threadIdx.x & 31;
    const int b     = gwarp >> 8;
    const int l     = gwarp & 255;

    const int fi   = frag[(b << 8) + l];
    const int segi = (fi == 2) ? 1 : fi;

    const float* drow = g_d2min + ((size_t)b << 16) + ((size_t)l << 8);
    const int*   frow = frag + (b << 8);

    u64 p0[8], p1[8];   // intra / inter key streams
#pragma unroll
    for (int u = 0; u < 8; u++) {
        const int j  = lane + (u << 5);
        const int fj = frow[j];
        const int segj = (fj == 2) ? 1 : fj;
        const bool same = (segj == segi);
        const float v = drow[j];
        const u64 key = ((u64)__float_as_uint(v) << 32) | (u32)j;
        const u64 inf = 0xffffffff00000000ULL | (u32)j;
        p0[u] = (same && j != l) ? key : inf;   // intra
        p1[u] = (!same)          ? key : inf;   // inter
    }

    SORT8(p0)
    SORT8(p1)

    const size_t base0 = (size_t)OFF_EDGES + EDGES_ROW + (size_t)((b << 8) + l) * Kk;
    const size_t base1 = base0 + EDGES_HALF;
    const float  boff  = (float)(b << 8);

#pragma unroll
    for (int k = 0; k < Kk; k++) {
        // stream 0 (intra) and stream 1 (inter): independent chains
        const u32 hd0 = (u32)(p0[0] >> 32);
        const u32 hd1 = (u32)(p1[0] >> 32);
        const u32 wd0 = __reduce_min_sync(0xffffffffu, hd0);
        const u32 wd1 = __reduce_min_sync(0xffffffffu, hd1);
        const u32 cj0 = (hd0 == wd0) ? (u32)p0[0] : 0xffffffffu;
        const u32 cj1 = (hd1 == wd1) ? (u32)p1[0] : 0xffffffffu;
        const u32 wj0 = __reduce_min_sync(0xffffffffu, cj0);
        const u32 wj1 = __reduce_min_sync(0xffffffffu, cj1);
        if (lane == 0) {
            out[base0 + k] = (float)wj0 + boff;
            out[base1 + k] = (float)wj1 + boff;
        }
        if (hd0 == wd0 && (u32)p0[0] == wj0) {
#pragma unroll
            for (int u = 0; u < 7; u++) p0[u] = p0[u + 1];
            p0[7] = ~0ULL;
        }
        if (hd1 == wd1 && (u32)p1[0] == wj1) {
#pragma unroll
            for (int u = 0; u < 7; u++) p1[u] = p1[u + 1];
            p1[7] = ~0ULL;
        }
    }
}

// ---------------------------------------------------------------------------
extern "C" void kernel_launch(void* const* d_in, const int* in_sizes, int n_in,
                              void* d_out, int out_size) {
    const float* pos      = (const float*)d_in[0];
    const int*   frag     = (const int*)  d_in[6];
    const float* edge_emb = (const float*)d_in[7];
    float* out = (float*)d_out;

    dist_kernel<<<DIST_CTAS, 256>>>(pos);
    knn_fill_kernel<<<KNN_CTAS + FILL4_CTAS, 256>>>(frag, edge_emb, out);

    (void)in_sizes; (void)n_in; (void)out_size;
}

// round 9
// speedup vs baseline: 1.3695x; 1.0137x over previous
#include <cuda_runtime.h>
#include <math_constants.h>

typedef unsigned long long u64;
typedef unsigned int u32;

// Problem constants
#define Bb 8
#define Ll 256
#define Aa 15
#define Kk 9
#define TB 16
#define NTILES 136                   // triangular 16x16 tiles per batch
#define DIST_CTAS (Bb * NTILES)      // 1088
#define KNN_CTAS  256                // 2048 warps: one per (b,l), both types
#define FILL_CTAS 680                // N_OUT/4/256 float4 fills
#define TOTAL_CTAS (DIST_CTAS + KNN_CTAS + FILL_CTAS)

// Output layout (float32, concatenated flattened tuple)
#define OFF_BATCH   30720
#define OFF_EDGES   32768
#define OFF_ATTR    106496
#define N_OUT       696320
#define EDGES_HALF  18432
#define EDGES_ROW   36864

// Scratch
__device__ float g_d2min[Bb * Ll * Ll];
__device__ u32   g_cnt[Bb];        // dist tiles completed per batch
__device__ u32   g_done[Bb];       // knn CTAs completed per batch (for reset)

static __device__ __forceinline__ u32 ld_acquire(const u32* p) {
    u32 v; asm volatile("ld.acquire.gpu.u32 %0, [%1];" : "=r"(v) : "l"(p) : "memory");
    return v;
}

#define CE(x, y) { u64 aa_ = x, bb_ = y; bool g_ = aa_ > bb_; x = g_ ? bb_ : aa_; y = g_ ? aa_ : bb_; }
#define SORT8(q) \
    CE(q[0],q[1]) CE(q[2],q[3]) CE(q[4],q[5]) CE(q[6],q[7]) \
    CE(q[0],q[2]) CE(q[1],q[3]) CE(q[4],q[6]) CE(q[5],q[7]) \
    CE(q[1],q[2]) CE(q[5],q[6]) \
    CE(q[0],q[4]) CE(q[1],q[5]) CE(q[2],q[6]) CE(q[3],q[7]) \
    CE(q[2],q[4]) CE(q[3],q[5]) \
    CE(q[1],q[2]) CE(q[3],q[4]) CE(q[5],q[6])

// ---------------------------------------------------------------------------
// ONE fused kernel. bid order: [dist tiles | knn | fill].
//  dist: triangular block-pair min half-squared-distance (rank-equivalent),
//        release-count into g_cnt[b] when its tile (both mirrors) is visible.
//  knn : acquire-spin until g_cnt[b]==NTILES, then dual-stream top-9 per row.
//        knn is the SOLE writer of the dst-edge region (no fill overlap!).
//  fill: static float4 output regions; skips the dst region entirely.
// ---------------------------------------------------------------------------
__global__ void __launch_bounds__(256) fused_kernel(const float* __restrict__ pos,
                                                    const int* __restrict__ frag,
                                                    const float* __restrict__ edge_emb,
                                                    float* __restrict__ out) {
    const int bid = blockIdx.x;
    const int t   = threadIdx.x;

    if (bid < DIST_CTAS) {
        // ================= DIST =================
        __shared__ float4 sI[TB * Aa];
        __shared__ float4 sJ[TB * Aa];

        const int b = bid / NTILES;
        int r = bid % NTILES, ti = 0;
        while (r >= (TB - ti)) { r -= (TB - ti); ti++; }
        const int tj = ti + r;
        const int i0 = ti * TB, j0 = tj * TB;

        if (t < TB * Aa) {
            const int blk = t / Aa;
            const int at  = t % Aa;
            {
                const float* p = pos + ((size_t)((b * Ll + i0 + blk) * Aa + at)) * 3;
                float x = p[0], y = p[1], z = p[2];
                sI[t] = make_float4(x, y, z, 0.5f * (x * x + y * y + z * z));
            }
            {
                const float* p = pos + ((size_t)((b * Ll + j0 + blk) * Aa + at)) * 3;
                float x = p[0], y = p[1], z = p[2];
                sJ[t] = make_float4(x, y, z, 0.5f * (x * x + y * y + z * z));
            }
        }
        __syncthreads();

        const int ii = t >> 4;
        const int jj = t & 15;

        float jx[Aa], jy[Aa], jz[Aa], jn[Aa];
#pragma unroll
        for (int a = 0; a < Aa; a++) {
            const float4 v = sJ[jj * Aa + a];
            jx[a] = v.x; jy[a] = v.y; jz[a] = v.z; jn[a] = v.w;
        }

        float m0 = CUDART_INF_F, m1 = CUDART_INF_F;
#pragma unroll
        for (int a = 0; a < Aa; a++) {
            const float4 I = sI[ii * Aa + a];
            float mA = fmaf(-I.z, jz[0], fmaf(-I.y, jy[0], fmaf(-I.x, jx[0], jn[0])));
            float mB = fmaf(-I.z, jz[1], fmaf(-I.y, jy[1], fmaf(-I.x, jx[1], jn[1])));
#pragma unroll
            for (int c = 2; c + 1 < Aa; c += 2) {
                mA = fminf(mA, fmaf(-I.z, jz[c],   fmaf(-I.y, jy[c],   fmaf(-I.x, jx[c],   jn[c]))));
                mB = fminf(mB, fmaf(-I.z, jz[c+1], fmaf(-I.y, jy[c+1], fmaf(-I.x, jx[c+1], jn[c+1]))));
            }
            mA = fminf(mA, fmaf(-I.z, jz[Aa-1], fmaf(-I.y, jy[Aa-1], fmaf(-I.x, jx[Aa-1], jn[Aa-1]))));
            const float mloc = fminf(mA, mB) + I.w;
            if (a & 1) m1 = fminf(m1, mloc); else m0 = fminf(m0, mloc);
        }
        const float m = fmaxf(fminf(m0, m1), 0.0f);

        float* g = g_d2min + (size_t)b * Ll * Ll;
        g[(size_t)(i0 + ii) * Ll + (j0 + jj)] = m;
        g[(size_t)(j0 + jj) * Ll + (i0 + ii)] = m;

        // release this tile
        __syncthreads();
        __threadfence();
        if (t == 0) atomicAdd(&g_cnt[b], 1u);
        return;
    }

    if (bid < DIST_CTAS + KNN_CTAS) {
        // ================= KNN =================
        const int kcta  = bid - DIST_CTAS;              // 0..255
        const int gwarp = (kcta << 3) + (t >> 5);       // 0..2047
        const int lane  = t & 31;
        const int b     = gwarp >> 8;                   // CTA-uniform
        const int l     = gwarp & 255;

        // wait for batch b's distance rows
        if (t == 0) {
            while (ld_acquire(&g_cnt[b]) < (u32)NTILES) __nanosleep(64);
        }
        __syncthreads();

        const int fi   = frag[(b << 8) + l];
        const int segi = (fi == 2) ? 1 : fi;

        const float* drow = g_d2min + ((size_t)b << 16) + ((size_t)l << 8);
        const int*   frow = frag + (b << 8);

        u64 p0[8], p1[8];
#pragma unroll
        for (int u = 0; u < 8; u++) {
            const int j  = lane + (u << 5);
            const int fj = frow[j];
            const int segj = (fj == 2) ? 1 : fj;
            const bool same = (segj == segi);
            const float v = drow[j];
            const u64 key = ((u64)__float_as_uint(v) << 32) | (u32)j;
            const u64 inf = 0xffffffff00000000ULL | (u32)j;
            p0[u] = (same && j != l) ? key : inf;   // intra
            p1[u] = (!same)          ? key : inf;   // inter
        }

        SORT8(p0)
        SORT8(p1)

        const size_t base0 = (size_t)OFF_EDGES + EDGES_ROW + (size_t)((b << 8) + l) * Kk;
        const size_t base1 = base0 + EDGES_HALF;
        const float  boff  = (float)(b << 8);

#pragma unroll
        for (int k = 0; k < Kk; k++) {
            const u32 hd0 = (u32)(p0[0] >> 32);
            const u32 hd1 = (u32)(p1[0] >> 32);
            const u32 wd0 = __reduce_min_sync(0xffffffffu, hd0);
            const u32 wd1 = __reduce_min_sync(0xffffffffu, hd1);
            const u32 cj0 = (hd0 == wd0) ? (u32)p0[0] : 0xffffffffu;
            const u32 cj1 = (hd1 == wd1) ? (u32)p1[0] : 0xffffffffu;
            const u32 wj0 = __reduce_min_sync(0xffffffffu, cj0);
            const u32 wj1 = __reduce_min_sync(0xffffffffu, cj1);
            if (lane == 0) {
                out[base0 + k] = (float)wj0 + boff;
                out[base1 + k] = (float)wj1 + boff;
            }
            if (hd0 == wd0 && (u32)p0[0] == wj0) {
#pragma unroll
                for (int u = 0; u < 7; u++) p0[u] = p0[u + 1];
                p0[7] = ~0ULL;
            }
            if (hd1 == wd1 && (u32)p1[0] == wj1) {
#pragma unroll
                for (int u = 0; u < 7; u++) p1[u] = p1[u + 1];
                p1[7] = ~0ULL;
            }
        }

        // last knn CTA of this batch resets the counters for the next replay
        __syncthreads();
        if (t == 0) {
            const u32 old = atomicAdd(&g_done[b], 1u);
            if (old == 31u) {              // 32 knn CTAs per batch
                g_cnt[b]  = 0u;
                g_done[b] = 0u;
            }
        }
        return;
    }

    // ================= FILL =================
    {
        const int q = (bid - DIST_CTAS - KNN_CTAS) * 256 + t;   // float4 index
        const int i = q << 2;
        if (i >= N_OUT) return;
        float4 v;
        if (i < OFF_BATCH) {
            v.x = (float)(i / Aa); v.y = (float)((i + 1) / Aa);
            v.z = (float)((i + 2) / Aa); v.w = (float)((i + 3) / Aa);
        } else if (i < OFF_EDGES) {
            const float bv = (float)((i - OFF_BATCH) >> 8);
            v.x = bv; v.y = bv; v.z = bv; v.w = bv;
        } else if (i < OFF_ATTR) {
            const int e = i - OFF_EDGES;
            if (e >= EDGES_ROW) return;   // dst row: knn is the SOLE writer (race fix)
            float s[4];
#pragma unroll
            for (int u = 0; u < 4; u++) {
                const int pu = (e + u) % EDGES_HALF;
                s[u] = (float)(((pu / Kk) % Ll) + (pu / (Ll * Kk)) * Ll);
            }
            v.x = s[0]; v.y = s[1]; v.z = s[2]; v.w = s[3];
        } else {
            const int e    = i - OFF_ATTR;
            const int type = ((e >> 4) >= EDGES_HALF) ? 1 : 0;
            v = *(const float4*)(edge_emb + type * 16 + (e & 12));
        }
        *(float4*)(out + i) = v;
    }
}

// ---------------------------------------------------------------------------
extern "C" void kernel_launch(void* const* d_in, const int* in_sizes, int n_in,
                              void* d_out, int out_size) {
    const float* pos      = (const float*)d_in[0];
    const int*   frag     = (const int*)  d_in[6];
    const float* edge_emb = (const float*)d_in[7];
    float* out = (float*)d_out;

    fused_kernel<<<TOTAL_CTAS, 256>>>(pos, frag, edge_emb, out);

    (void)in_sizes; (void)n_in; (void)out_size;
}